// round 2
// baseline (speedup 1.0000x reference)
#include <cuda_runtime.h>
#include <cuda_bf16.h>
#include <cstdint>
#include <cstddef>

// ---------------------------------------------------------------------------
// SCAEAttention: restructured through the rank-64 (head-dim) factorization.
//
// Shapes: B=4, S=256, H=12, DH=64, D=768, FD=2048, FU=2048
//
//  E[h,k,f]   = sum_o W_O[h,k,o] * enc_W[f,o]                  [12,64,2048]
//  P[h,k,u]   = sum_i W_V[h,i,k] * up_dec_W[i,u]               [12,64,2048]
//  virtual[h,f,u] = mask[f,u] * sum_k E[h,k,f]*P[h,k,u]        [12,2048,2048]
//  act_ln     = resid/ln ; up_ln = pruned/ln ; inv = 1/ln
//  t2[h,bs,k] = act_ln @ W_V[h]                                [12,1024,64]
//  S1[b,h,q,c]= probs[b,h] @ t2[h, b-rows]                     [4,12,256,64]
//  R[b,h,q,u] = probs[b,h] @ up_ln[b]                          [4,12,256,2048]
//  out[b,q,f] = sum_h ( S1[b,h] @ E[h]  +  R[b,h] @ virtual[h]^T )
//             + bias0[f] + inv[b,q]*g[f]
//  bias0[f]   = enc_b[f] - enc_W@b_dec
//  g[f]       = enc_W @ C,  C[d] = sum_{h,k} (W_V[h]^T up_b_dec)[k] * W_O[h,k,d]
// ---------------------------------------------------------------------------

#define HN 12
#define DHN 64
#define DN 768
#define FDN 2048
#define FUN 2048
#define BSN 1024   // B*S

__device__ float g_E[HN * DHN * FDN];          // [h][k][f]
__device__ float g_P[HN * DHN * FUN];          // [h][k][u]
__device__ float g_virtual[HN * FDN * FUN];    // [h][f][u]  (201 MB)
__device__ float g_t2[HN * BSN * DHN];         // [h][b*s][k]
__device__ float g_S1[4 * HN * 256 * DHN];     // [b][h][q][c]
__device__ float g_R[4 * HN * 256 * FUN];      // [b][h][q][u] (100 MB)
__device__ float g_actln[BSN * DN];
__device__ float g_upln[BSN * FUN];
__device__ float g_inv[BSN];
__device__ float g_v[HN * DHN];
__device__ float g_C[DN];
__device__ float g_gvec[FDN];
__device__ float g_bias0[FDN];

#define PADW 4

// --------------------------- shared GEMM core ------------------------------
// C(m,n) += sum_k A(m,k)*B(k,n); TA: A(m,k)=A[k*lda+m], TB: B(k,n)=B[n*ldb+k]
template <int BM, int BN, int BK, int TM, int TN, bool TA, bool TB>
__device__ __forceinline__ void gemm_core(
    const float* __restrict__ A, int lda,
    const float* __restrict__ B, int ldb,
    int K, int tileM, int tileN,
    float (&acc)[TM][TN],
    float (*As)[BM + PADW], float (*Bs)[BN + PADW])
{
    const int tid = threadIdx.x;
    const int NX = BN / TN;
    const int tx = tid % NX;
    const int ty = tid / NX;

    for (int k0 = 0; k0 < K; k0 += BK) {
#pragma unroll
        for (int r = 0; r < (BM * BK) / 256; ++r) {
            int i = tid + r * 256;
            if (TA) {
                int k = i / BM, m = i - k * BM;
                As[k][m] = A[(size_t)(k0 + k) * lda + tileM + m];
            } else {
                int m = i / BK, k = i - m * BK;
                As[k][m] = A[(size_t)(tileM + m) * lda + k0 + k];
            }
        }
#pragma unroll
        for (int r = 0; r < (BN * BK) / 256; ++r) {
            int i = tid + r * 256;
            if (TB) {
                int n = i / BK, k = i - n * BK;
                Bs[k][n] = B[(size_t)(tileN + n) * ldb + k0 + k];
            } else {
                int k = i / BN, n = i - k * BN;
                Bs[k][n] = B[(size_t)(k0 + k) * ldb + tileN + n];
            }
        }
        __syncthreads();
#pragma unroll
        for (int kk = 0; kk < BK; ++kk) {
            float ar[TM], br[TN];
#pragma unroll
            for (int i = 0; i < TM; i++) ar[i] = As[kk][ty * TM + i];
#pragma unroll
            for (int j = 0; j < TN; j++) br[j] = Bs[kk][tx * TN + j];
#pragma unroll
            for (int i = 0; i < TM; i++)
#pragma unroll
                for (int j = 0; j < TN; j++)
                    acc[i][j] = fmaf(ar[i], br[j], acc[i][j]);
        }
        __syncthreads();
    }
}

// --------------------------- generic GEMM kernel ---------------------------
// batch index bz -> (bo = bz/bsplit, bi = bz%bsplit), offsets bo*sXo + bi*sXi
template <int BM, int BN, int BK, int TM, int TN, bool TA, bool TB>
__global__ void __launch_bounds__(256) gemm_kernel(
    const float* __restrict__ A, int lda, long sAo, long sAi,
    const float* __restrict__ B, int ldb, long sBo, long sBi,
    float* __restrict__ C, int ldc, long sCo, long sCi,
    int K, int bsplit,
    const int* __restrict__ mask, int mld)
{
    __shared__ float As[BK][BM + PADW];
    __shared__ float Bs[BK][BN + PADW];

    int bz = blockIdx.z;
    int bo = bz / bsplit, bi = bz - bo * bsplit;
    A += bo * sAo + bi * sAi;
    B += bo * sBo + bi * sBi;
    C += bo * sCo + bi * sCi;

    int tileM = blockIdx.y * BM;
    int tileN = blockIdx.x * BN;

    float acc[TM][TN] = {};
    gemm_core<BM, BN, BK, TM, TN, TA, TB>(A, lda, B, ldb, K, tileM, tileN, acc, As, Bs);

    const int NX = BN / TN;
    int tx = threadIdx.x % NX;
    int ty = threadIdx.x / NX;

    if (mask != nullptr) {
#pragma unroll
        for (int i = 0; i < TM; i++) {
            int m = tileM + ty * TM + i;
#pragma unroll
            for (int j = 0; j < TN; j++) {
                int n = tileN + tx * TN + j;
                C[(size_t)m * ldc + n] = acc[i][j] * (float)mask[(size_t)m * mld + n];
            }
        }
    } else {
#pragma unroll
        for (int i = 0; i < TM; i++) {
            int m = tileM + ty * TM + i;
#pragma unroll
            for (int j = 0; j < TN; j++) {
                int n = tileN + tx * TN + j;
                C[(size_t)m * ldc + n] = acc[i][j];
            }
        }
    }
}

// --------------------------- final fused kernel ----------------------------
// out[b,q,f] = sum_h (S1[b,h] @ E[h]  (K=64)  +  R[b,h] @ virtual[h]^T (K=2048))
//            + bias0[f] + inv[b,q]*g[f]
__global__ void __launch_bounds__(256) final_kernel(float* __restrict__ out)
{
    constexpr int BM = 128, BN = 128, BK = 16, TM = 8, TN = 8;
    __shared__ float As[BK][BM + PADW];
    __shared__ float Bs[BK][BN + PADW];

    const int b = blockIdx.z;
    const int tileM = blockIdx.y * BM;   // q within this batch's 256
    const int tileN = blockIdx.x * BN;   // f

    float acc[TM][TN] = {};

    for (int h = 0; h < HN; ++h) {
        const float* A1 = g_S1 + ((size_t)(b * HN + h)) * 256 * DHN;
        const float* B1 = g_E + (size_t)h * DHN * FDN;
        gemm_core<BM, BN, BK, TM, TN, false, false>(A1, DHN, B1, FDN, DHN,
                                                    tileM, tileN, acc, As, Bs);
        const float* A2 = g_R + ((size_t)(b * HN + h)) * 256 * FUN;
        const float* B2 = g_virtual + (size_t)h * FDN * FUN;
        gemm_core<BM, BN, BK, TM, TN, false, true>(A2, FUN, B2, FUN, FUN,
                                                   tileM, tileN, acc, As, Bs);
    }

    const int NX = BN / TN;
    int tx = threadIdx.x % NX;
    int ty = threadIdx.x / NX;
#pragma unroll
    for (int i = 0; i < TM; i++) {
        int q = tileM + ty * TM + i;
        float invq = g_inv[b * 256 + q];
#pragma unroll
        for (int j = 0; j < TN; j++) {
            int f = tileN + tx * TN + j;
            out[((size_t)b * 256 + q) * FDN + f] =
                acc[i][j] + g_bias0[f] + invq * g_gvec[f];
        }
    }
}

// --------------------------- small kernels ---------------------------------
__global__ void prep_kernel(const float* __restrict__ resid,
                            const float* __restrict__ ln,
                            const float* __restrict__ pruned)
{
    int row = blockIdx.x;                 // 0..1023 = b*256+s
    float inv = 1.0f / ln[row];
    if (threadIdx.x == 0) g_inv[row] = inv;
    for (int d = threadIdx.x; d < DN; d += blockDim.x)
        g_actln[(size_t)row * DN + d] = resid[(size_t)row * DN + d] * inv;
    for (int u = threadIdx.x; u < FUN; u += blockDim.x)
        g_upln[(size_t)row * FUN + u] = pruned[(size_t)row * FUN + u] * inv;
}

__global__ void bias_v_kernel(const float* __restrict__ W_V,
                              const float* __restrict__ up_b_dec)
{
    int hk = blockIdx.x * blockDim.x + threadIdx.x;   // 768
    if (hk >= HN * DHN) return;
    int h = hk >> 6, k = hk & 63;
    const float* base = W_V + (size_t)h * DN * DHN + k;
    float s = 0.f;
    for (int m = 0; m < DN; m++) s = fmaf(base[(size_t)m * DHN], up_b_dec[m], s);
    g_v[hk] = s;
}

__global__ void bias_C_kernel(const float* __restrict__ W_O)
{
    int d = blockIdx.x * blockDim.x + threadIdx.x;    // 768
    if (d >= DN) return;
    float s = 0.f;
    for (int hk = 0; hk < HN * DHN; hk++)
        s = fmaf(g_v[hk], W_O[(size_t)hk * DN + d], s);
    g_C[d] = s;
}

__global__ void bias_g_kernel(const float* __restrict__ enc_W,
                              const float* __restrict__ enc_b,
                              const float* __restrict__ b_dec)
{
    int f = blockIdx.x * blockDim.x + threadIdx.x;    // 2048
    if (f >= FDN) return;
    const float* row = enc_W + (size_t)f * DN;
    float sg = 0.f, sb = 0.f;
    for (int d = 0; d < DN; d++) {
        sg = fmaf(row[d], g_C[d], sg);
        sb = fmaf(row[d], b_dec[d], sb);
    }
    g_gvec[f] = sg;
    g_bias0[f] = enc_b[f] - sb;
}

// --------------------------- launch ----------------------------------------
extern "C" void kernel_launch(void* const* d_in, const int* in_sizes, int n_in,
                              void* d_out, int out_size)
{
    (void)in_sizes; (void)n_in; (void)out_size;
    const float* resid    = (const float*)d_in[0];   // [4,256,768]
    const float* ln       = (const float*)d_in[1];   // [4,256,1]
    const float* probs    = (const float*)d_in[2];   // [4,12,256,256]
    const float* W_O      = (const float*)d_in[3];   // [12,64,768]
    const float* W_V      = (const float*)d_in[4];   // [12,768,64]
    const float* enc_W    = (const float*)d_in[5];   // [2048,768]
    const float* enc_b    = (const float*)d_in[6];   // [2048]
    const float* b_dec    = (const float*)d_in[7];   // [768]
    const float* up_dec_W = (const float*)d_in[8];   // [768,2048]
    const float* up_b_dec = (const float*)d_in[9];   // [768]
    const float* pruned   = (const float*)d_in[10];  // [4,256,2048]
    const int*   cmask    = (const int*)d_in[11];    // [2048,2048]
    float* out = (float*)d_out;                      // [4,256,2048]

    float *pE, *pP, *pT2, *pV, *pS1, *pR, *pAct, *pUp;
    cudaGetSymbolAddress((void**)&pE,  g_E);
    cudaGetSymbolAddress((void**)&pP,  g_P);
    cudaGetSymbolAddress((void**)&pT2, g_t2);
    cudaGetSymbolAddress((void**)&pV,  g_virtual);
    cudaGetSymbolAddress((void**)&pS1, g_S1);
    cudaGetSymbolAddress((void**)&pR,  g_R);
    cudaGetSymbolAddress((void**)&pAct, g_actln);
    cudaGetSymbolAddress((void**)&pUp,  g_upln);

    // elementwise prep + rank-1 bias chain
    prep_kernel<<<BSN, 256>>>(resid, ln, pruned);
    bias_v_kernel<<<3, 256>>>(W_V, up_b_dec);
    bias_C_kernel<<<3, 256>>>(W_O);
    bias_g_kernel<<<8, 256>>>(enc_W, enc_b, b_dec);

    // E[h] = W_O[h] @ enc_W^T : M=64,N=2048,K=768 (NT)
    gemm_kernel<64,128,16,4,8,false,true><<<dim3(16,1,HN), 256>>>(
        W_O, DN, (long)DHN*DN, 0,
        enc_W, DN, 0, 0,
        pE, FDN, (long)DHN*FDN, 0,
        DN, 1, nullptr, 0);

    // P[h] = W_V[h]^T @ up_dec_W : M=64,N=2048,K=768 (TN)
    gemm_kernel<64,128,16,4,8,true,false><<<dim3(16,1,HN), 256>>>(
        W_V, DHN, (long)DN*DHN, 0,
        up_dec_W, FUN, 0, 0,
        pP, FUN, (long)DHN*FUN, 0,
        DN, 1, nullptr, 0);

    // t2[h] = act_ln @ W_V[h] : M=1024,N=64,K=768 (NN)
    gemm_kernel<128,64,16,8,4,false,false><<<dim3(1,8,HN), 256>>>(
        pAct, DN, 0, 0,
        W_V, DHN, (long)DN*DHN, 0,
        pT2, DHN, (long)BSN*DHN, 0,
        DN, 1, nullptr, 0);

    // virtual[h] = mask .* (E[h]^T @ P[h]) : M=2048,N=2048,K=64 (TN) + mask
    gemm_kernel<128,128,16,8,8,true,false><<<dim3(16,16,HN), 256>>>(
        pE, FDN, (long)DHN*FDN, 0,
        pP, FUN, (long)DHN*FUN, 0,
        pV, FUN, (long)FDN*FUN, 0,
        DHN, 1, cmask, FUN);

    // S1[b,h] = probs[b,h] @ t2[h, b-rows] : M=256,N=64,K=256 (NN), bz=b*12+h
    gemm_kernel<128,64,16,8,4,false,false><<<dim3(1,2,4*HN), 256>>>(
        probs, 256, (long)HN*256*256, (long)256*256,
        pT2, DHN, (long)256*DHN, (long)BSN*DHN,
        pS1, DHN, (long)HN*256*DHN, (long)256*DHN,
        256, HN, nullptr, 0);

    // R[b,h] = probs[b,h] @ up_ln[b] : M=256,N=2048,K=256 (NN), bz=b*12+h
    gemm_kernel<128,128,16,8,8,false,false><<<dim3(16,2,4*HN), 256>>>(
        probs, 256, (long)HN*256*256, (long)256*256,
        pUp, FUN, (long)256*FUN, 0,
        pR, FUN, (long)HN*256*FUN, (long)256*FUN,
        256, HN, nullptr, 0);

    // out = sum_h (S1@E + R@virtual^T) + bias
    final_kernel<<<dim3(16,2,4), 256>>>(out);
}